// round 1
// baseline (speedup 1.0000x reference)
#include <cuda_runtime.h>
#include <cstdint>

// Ragged segment mean:
//   seq:   [B=2048, L=512, D=512] float32
//   begin: [B] int32
//   end:   [B] int32
//   out:   [B, D] float32,  out[b] = mean(seq[b, begin[b]:end[b]], axis=0)
//
// One CTA per batch row. 128 threads x float4 covers D=512.
// Row loop unrolled x4 with independent accumulators for MLP.

static constexpr int L = 512;
static constexpr int D = 512;
static constexpr int D4 = D / 4;        // 128 float4 per row
static constexpr int THREADS = D4;      // 128

__global__ __launch_bounds__(THREADS, 8)
void ragged_mean_kernel(const float4* __restrict__ seq,
                        const int* __restrict__ begin,
                        const int* __restrict__ end,
                        float4* __restrict__ out) {
    const int b = blockIdx.x;
    const int t = threadIdx.x;

    const int s = begin[b];
    const int e = end[b];
    const int n = e - s;

    // base pointer for this (batch, d-chunk); row stride = D4 float4
    const float4* __restrict__ base =
        seq + (size_t)b * (L * (size_t)D4) + t;

    float4 a0 = make_float4(0.f, 0.f, 0.f, 0.f);
    float4 a1 = make_float4(0.f, 0.f, 0.f, 0.f);
    float4 a2 = make_float4(0.f, 0.f, 0.f, 0.f);
    float4 a3 = make_float4(0.f, 0.f, 0.f, 0.f);

    int r = s;
    // unrolled x4: 4 independent in-flight loads per thread
    for (; r + 4 <= e; r += 4) {
        float4 v0 = __ldg(base + (size_t)(r + 0) * D4);
        float4 v1 = __ldg(base + (size_t)(r + 1) * D4);
        float4 v2 = __ldg(base + (size_t)(r + 2) * D4);
        float4 v3 = __ldg(base + (size_t)(r + 3) * D4);
        a0.x += v0.x; a0.y += v0.y; a0.z += v0.z; a0.w += v0.w;
        a1.x += v1.x; a1.y += v1.y; a1.z += v1.z; a1.w += v1.w;
        a2.x += v2.x; a2.y += v2.y; a2.z += v2.z; a2.w += v2.w;
        a3.x += v3.x; a3.y += v3.y; a3.z += v3.z; a3.w += v3.w;
    }
    for (; r < e; ++r) {
        float4 v = __ldg(base + (size_t)r * D4);
        a0.x += v.x; a0.y += v.y; a0.z += v.z; a0.w += v.w;
    }

    const float inv = 1.0f / (float)n;
    float4 res;
    res.x = (a0.x + a1.x + a2.x + a3.x) * inv;
    res.y = (a0.y + a1.y + a2.y + a3.y) * inv;
    res.z = (a0.z + a1.z + a2.z + a3.z) * inv;
    res.w = (a0.w + a1.w + a2.w + a3.w) * inv;

    out[(size_t)b * D4 + t] = res;
}

extern "C" void kernel_launch(void* const* d_in, const int* in_sizes, int n_in,
                              void* d_out, int out_size) {
    const float4* seq  = (const float4*)d_in[0];
    const int* begin   = (const int*)d_in[1];
    const int* end     = (const int*)d_in[2];
    float4* out        = (float4*)d_out;

    const int B = in_sizes[1];  // 2048
    ragged_mean_kernel<<<B, THREADS>>>(seq, begin, end, out);
}

// round 2
// speedup vs baseline: 1.1147x; 1.1147x over previous
#include <cuda_runtime.h>
#include <cstdint>

// Ragged segment mean, chunk-balanced:
//   seq:   [B=2048, L=512, D=512] float32
//   out[b] = mean(seq[b, begin[b]:end[b]], axis=0)
//
// Grid = (B, L/CHUNK). CTA (b, c) sums rows of chunk c intersected with
// [begin[b], end[b]), scales by 1/n, and red.global.add.v4.f32 into out[b].
// Max 32 rows per CTA -> ragged imbalance bounded by one chunk.
// Output zeroed by cudaMemsetAsync (graph-capturable).

static constexpr int L = 512;
static constexpr int D = 512;
static constexpr int D4 = D / 4;        // 128 float4 per row
static constexpr int THREADS = D4;      // 128
static constexpr int CHUNK = 32;
static constexpr int NCHUNK = L / CHUNK; // 16

__device__ __forceinline__ void red_add_v4(float* addr, float4 v) {
    asm volatile("red.global.add.v4.f32 [%0], {%1, %2, %3, %4};"
                 :: "l"(addr), "f"(v.x), "f"(v.y), "f"(v.z), "f"(v.w)
                 : "memory");
}

__global__ __launch_bounds__(THREADS)
void ragged_mean_chunk_kernel(const float4* __restrict__ seq,
                              const int* __restrict__ begin,
                              const int* __restrict__ end,
                              float* __restrict__ out) {
    const int b = blockIdx.x;
    const int c = blockIdx.y;

    const int s = begin[b];
    const int e = end[b];

    const int lo = max(s, c * CHUNK);
    const int hi = min(e, (c + 1) * CHUNK);
    if (lo >= hi) return;  // chunk outside segment

    const float inv = 1.0f / (float)(e - s);
    const int t = threadIdx.x;

    const float4* __restrict__ base =
        seq + (size_t)b * (L * (size_t)D4) + t;

    float4 a0 = make_float4(0.f, 0.f, 0.f, 0.f);
    float4 a1 = make_float4(0.f, 0.f, 0.f, 0.f);
    float4 a2 = make_float4(0.f, 0.f, 0.f, 0.f);
    float4 a3 = make_float4(0.f, 0.f, 0.f, 0.f);

    int r = lo;
    for (; r + 4 <= hi; r += 4) {
        float4 v0 = __ldg(base + (size_t)(r + 0) * D4);
        float4 v1 = __ldg(base + (size_t)(r + 1) * D4);
        float4 v2 = __ldg(base + (size_t)(r + 2) * D4);
        float4 v3 = __ldg(base + (size_t)(r + 3) * D4);
        a0.x += v0.x; a0.y += v0.y; a0.z += v0.z; a0.w += v0.w;
        a1.x += v1.x; a1.y += v1.y; a1.z += v1.z; a1.w += v1.w;
        a2.x += v2.x; a2.y += v2.y; a2.z += v2.z; a2.w += v2.w;
        a3.x += v3.x; a3.y += v3.y; a3.z += v3.z; a3.w += v3.w;
    }
    for (; r < hi; ++r) {
        float4 v = __ldg(base + (size_t)r * D4);
        a0.x += v.x; a0.y += v.y; a0.z += v.z; a0.w += v.w;
    }

    float4 p;
    p.x = (a0.x + a1.x + a2.x + a3.x) * inv;
    p.y = (a0.y + a1.y + a2.y + a3.y) * inv;
    p.z = (a0.z + a1.z + a2.z + a3.z) * inv;
    p.w = (a0.w + a1.w + a2.w + a3.w) * inv;

    red_add_v4(out + ((size_t)b * D4 + t) * 4, p);
}

extern "C" void kernel_launch(void* const* d_in, const int* in_sizes, int n_in,
                              void* d_out, int out_size) {
    const float4* seq  = (const float4*)d_in[0];
    const int* begin   = (const int*)d_in[1];
    const int* end     = (const int*)d_in[2];
    float* out         = (float*)d_out;

    const int B = in_sizes[1];  // 2048

    cudaMemsetAsync(d_out, 0, (size_t)out_size * sizeof(float));

    dim3 grid(B, NCHUNK);
    ragged_mean_chunk_kernel<<<grid, THREADS>>>(seq, begin, end, out);
}

// round 3
// speedup vs baseline: 1.1406x; 1.0232x over previous
#include <cuda_runtime.h>
#include <cstdint>

// Ragged segment mean, chunk-balanced, deep-MLP:
//   seq: [B=2048, L=512, D=512] f32; out[b] = mean(seq[b, begin[b]:end[b]])
//
// Grid = (B, L/CHUNK). CTA (b,c) sums chunk c ∩ [begin,end), pre-scales by
// 1/n, RED.v4 into out. Unroll x8: 8 independent LDG.128 in flight per
// thread (~36KB/SM in flight > BDP) to saturate HBM.

static constexpr int L = 512;
static constexpr int D = 512;
static constexpr int D4 = D / 4;         // 128 float4 per row
static constexpr int THREADS = D4;       // 128
static constexpr int CHUNK = 32;
static constexpr int NCHUNK = L / CHUNK; // 16

__device__ __forceinline__ void red_add_v4(float* addr, float4 v) {
    asm volatile("red.global.add.v4.f32 [%0], {%1, %2, %3, %4};"
                 :: "l"(addr), "f"(v.x), "f"(v.y), "f"(v.z), "f"(v.w)
                 : "memory");
}

__device__ __forceinline__ void acc4(float4& a, const float4& v) {
    a.x += v.x; a.y += v.y; a.z += v.z; a.w += v.w;
}

__global__ __launch_bounds__(THREADS)
void ragged_mean_chunk_kernel(const float4* __restrict__ seq,
                              const int* __restrict__ begin,
                              const int* __restrict__ end,
                              float* __restrict__ out) {
    const int b = blockIdx.x;
    const int c = blockIdx.y;

    const int s = begin[b];
    const int e = end[b];

    const int lo = max(s, c * CHUNK);
    const int hi = min(e, (c + 1) * CHUNK);
    if (lo >= hi) return;

    const float inv = 1.0f / (float)(e - s);
    const int t = threadIdx.x;

    const float4* __restrict__ base =
        seq + (size_t)b * (L * (size_t)D4) + t;

    float4 a0 = make_float4(0.f, 0.f, 0.f, 0.f);
    float4 a1 = make_float4(0.f, 0.f, 0.f, 0.f);
    float4 a2 = make_float4(0.f, 0.f, 0.f, 0.f);
    float4 a3 = make_float4(0.f, 0.f, 0.f, 0.f);

    int r = lo;
    // x8 unroll: 8 independent loads in flight per thread
    for (; r + 8 <= hi; r += 8) {
        float4 v0 = __ldg(base + (size_t)(r + 0) * D4);
        float4 v1 = __ldg(base + (size_t)(r + 1) * D4);
        float4 v2 = __ldg(base + (size_t)(r + 2) * D4);
        float4 v3 = __ldg(base + (size_t)(r + 3) * D4);
        float4 v4 = __ldg(base + (size_t)(r + 4) * D4);
        float4 v5 = __ldg(base + (size_t)(r + 5) * D4);
        float4 v6 = __ldg(base + (size_t)(r + 6) * D4);
        float4 v7 = __ldg(base + (size_t)(r + 7) * D4);
        acc4(a0, v0); acc4(a1, v1); acc4(a2, v2); acc4(a3, v3);
        acc4(a0, v4); acc4(a1, v5); acc4(a2, v6); acc4(a3, v7);
    }
    for (; r + 4 <= hi; r += 4) {
        float4 v0 = __ldg(base + (size_t)(r + 0) * D4);
        float4 v1 = __ldg(base + (size_t)(r + 1) * D4);
        float4 v2 = __ldg(base + (size_t)(r + 2) * D4);
        float4 v3 = __ldg(base + (size_t)(r + 3) * D4);
        acc4(a0, v0); acc4(a1, v1); acc4(a2, v2); acc4(a3, v3);
    }
    for (; r < hi; ++r) {
        float4 v = __ldg(base + (size_t)r * D4);
        acc4(a0, v);
    }

    float4 p;
    p.x = (a0.x + a1.x + a2.x + a3.x) * inv;
    p.y = (a0.y + a1.y + a2.y + a3.y) * inv;
    p.z = (a0.z + a1.z + a2.z + a3.z) * inv;
    p.w = (a0.w + a1.w + a2.w + a3.w) * inv;

    red_add_v4(out + ((size_t)b * D4 + t) * 4, p);
}

extern "C" void kernel_launch(void* const* d_in, const int* in_sizes, int n_in,
                              void* d_out, int out_size) {
    const float4* seq  = (const float4*)d_in[0];
    const int* begin   = (const int*)d_in[1];
    const int* end     = (const int*)d_in[2];
    float* out         = (float*)d_out;

    const int B = in_sizes[1];  // 2048

    cudaMemsetAsync(d_out, 0, (size_t)out_size * sizeof(float));

    dim3 grid(B, NCHUNK);
    ragged_mean_chunk_kernel<<<grid, THREADS>>>(seq, begin, end, out);
}

// round 5
// speedup vs baseline: 1.1578x; 1.0151x over previous
#include <cuda_runtime.h>
#include <cstdint>

// Ragged segment mean via TMA bulk-copy double-buffered streaming.
//   seq: [B=2048, L=512, D=512] f32; out[b] = mean(seq[b, begin[b]:end[b]])
//
// Grid = (B, L/64). CTA (b,c) covers chunk c (64 rows) ∩ [begin,end).
// The chunk's rows are CONTIGUOUS in memory (row = 2KB), so each 8-row
// stage is one 16KB cp.async.bulk into SMEM. Two buffers, mbarrier
// completion, reduce from SMEM, pre-scale by 1/n, RED.v4 into out.

static constexpr int L = 512;
static constexpr int D = 512;
static constexpr int D4 = D / 4;            // 128 float4 per row
static constexpr int THREADS = 128;
static constexpr int CHUNK = 64;
static constexpr int NCHUNK = L / CHUNK;    // 8
static constexpr int SROWS = 8;             // rows per stage (16KB)
static constexpr int ROW_BYTES = D * 4;     // 2048

__device__ __forceinline__ uint32_t smem_u32(const void* p) {
    return (uint32_t)__cvta_generic_to_shared(p);
}
__device__ __forceinline__ void mbar_init(uint32_t a, uint32_t cnt) {
    asm volatile("mbarrier.init.shared.b64 [%0], %1;" :: "r"(a), "r"(cnt) : "memory");
}
__device__ __forceinline__ void mbar_expect_tx(uint32_t a, uint32_t bytes) {
    asm volatile("mbarrier.arrive.expect_tx.shared.b64 _, [%0], %1;"
                 :: "r"(a), "r"(bytes) : "memory");
}
__device__ __forceinline__ void mbar_wait(uint32_t a, uint32_t parity) {
    uint32_t done;
    asm volatile("{\n\t.reg .pred p;\n\t"
                 "mbarrier.try_wait.parity.acquire.cta.shared::cta.b64 p, [%1], %2;\n\t"
                 "selp.b32 %0, 1, 0, p;\n\t}"
                 : "=r"(done) : "r"(a), "r"(parity) : "memory");
    while (!done) {
        asm volatile("{\n\t.reg .pred p;\n\t"
                     "mbarrier.try_wait.parity.acquire.cta.shared::cta.b64 p, [%1], %2, 10000000;\n\t"
                     "selp.b32 %0, 1, 0, p;\n\t}"
                     : "=r"(done) : "r"(a), "r"(parity) : "memory");
    }
}
__device__ __forceinline__ void bulk_g2s(uint32_t dst, const void* src,
                                         uint32_t bytes, uint32_t mbar) {
    asm volatile("cp.async.bulk.shared::cluster.global.mbarrier::complete_tx::bytes "
                 "[%0], [%1], %2, [%3];"
                 :: "r"(dst), "l"(src), "r"(bytes), "r"(mbar) : "memory");
}
__device__ __forceinline__ void red_add_v4(float* addr, float4 v) {
    asm volatile("red.global.add.v4.f32 [%0], {%1, %2, %3, %4};"
                 :: "l"(addr), "f"(v.x), "f"(v.y), "f"(v.z), "f"(v.w)
                 : "memory");
}

// Issue stage k: bulk copy rows [k*SROWS, k*SROWS+nr) of this chunk.
__device__ __forceinline__ void issue_stage(int k, int nrows,
                                            const char* src_base,
                                            uint32_t buf0, uint32_t buf1,
                                            uint32_t mb0, uint32_t mb1) {
    const int r0 = k * SROWS;
    const int nr = min(SROWS, nrows - r0);
    const uint32_t bytes = (uint32_t)nr * ROW_BYTES;
    const uint32_t dst = (k & 1) ? buf1 : buf0;
    const uint32_t mb  = (k & 1) ? mb1 : mb0;
    mbar_expect_tx(mb, bytes);
    bulk_g2s(dst, src_base + (size_t)r0 * ROW_BYTES, bytes, mb);
}

__global__ __launch_bounds__(THREADS)
void ragged_mean_tma_kernel(const float* __restrict__ seq,
                            const int* __restrict__ begin,
                            const int* __restrict__ end,
                            float* __restrict__ out) {
    __shared__ alignas(1024) float4 buf[2][SROWS * D4];  // 2 x 16KB
    __shared__ alignas(8) uint64_t mbar_s[2];

    const int b = blockIdx.x;
    const int c = blockIdx.y;
    const int s = begin[b];
    const int e = end[b];

    const int lo = max(s, c * CHUNK);
    const int hi = min(e, (c + 1) * CHUNK);
    if (lo >= hi) return;

    const int nrows = hi - lo;
    const int nstages = (nrows + SROWS - 1) / SROWS;
    const int t = threadIdx.x;

    const uint32_t mb0 = smem_u32(&mbar_s[0]);
    const uint32_t mb1 = smem_u32(&mbar_s[1]);
    const uint32_t buf0 = smem_u32(&buf[0][0]);
    const uint32_t buf1 = smem_u32(&buf[1][0]);

    if (t == 0) { mbar_init(mb0, 1); mbar_init(mb1, 1); }
    __syncthreads();

    const char* src_base =
        (const char*)seq + ((size_t)b * L + (size_t)lo) * ROW_BYTES;

    if (t == 0) {
        issue_stage(0, nrows, src_base, buf0, buf1, mb0, mb1);
        if (nstages > 1)
            issue_stage(1, nrows, src_base, buf0, buf1, mb0, mb1);
    }

    float4 a0 = make_float4(0.f, 0.f, 0.f, 0.f);
    float4 a1 = make_float4(0.f, 0.f, 0.f, 0.f);

    for (int k = 0; k < nstages; ++k) {
        mbar_wait((k & 1) ? mb1 : mb0, (k >> 1) & 1);

        const int r0 = k * SROWS;
        const int nr = min(SROWS, nrows - r0);
        const float4* bp = &buf[k & 1][t];

        if (nr == SROWS) {
            #pragma unroll
            for (int r = 0; r < SROWS; r += 2) {
                float4 v0 = bp[(r + 0) * D4];
                float4 v1 = bp[(r + 1) * D4];
                a0.x += v0.x; a0.y += v0.y; a0.z += v0.z; a0.w += v0.w;
                a1.x += v1.x; a1.y += v1.y; a1.z += v1.z; a1.w += v1.w;
            }
        } else {
            for (int r = 0; r < nr; ++r) {
                float4 v = bp[r * D4];
                a0.x += v.x; a0.y += v.y; a0.z += v.z; a0.w += v.w;
            }
        }

        if (k + 2 < nstages) {
            __syncthreads();  // everyone done reading this buffer
            if (t == 0)
                issue_stage(k + 2, nrows, src_base, buf0, buf1, mb0, mb1);
        }
    }

    const float inv = 1.0f / (float)(e - s);
    float4 p;
    p.x = (a0.x + a1.x) * inv;
    p.y = (a0.y + a1.y) * inv;
    p.z = (a0.z + a1.z) * inv;
    p.w = (a0.w + a1.w) * inv;

    red_add_v4(out + ((size_t)b * D4 + t) * 4, p);
}

extern "C" void kernel_launch(void* const* d_in, const int* in_sizes, int n_in,
                              void* d_out, int out_size) {
    const float* seq  = (const float*)d_in[0];
    const int* begin  = (const int*)d_in[1];
    const int* end    = (const int*)d_in[2];
    float* out        = (float*)d_out;

    const int B = in_sizes[1];  // 2048

    cudaMemsetAsync(d_out, 0, (size_t)out_size * sizeof(float));

    dim3 grid(B, NCHUNK);
    ragged_mean_tma_kernel<<<grid, THREADS>>>(seq, begin, end, out);
}